// round 16
// baseline (speedup 1.0000x reference)
#include <cuda_runtime.h>
#include <cuda_bf16.h>
#include <math.h>

#define NN 64
#define BATCH 4096
#define TPB 256
#define NBLK (BATCH / (TPB / 32))   // 512 blocks, one batch per warp, 4096 warps
#define NWARPS BATCH
#define EPS_PEN 0.1f
// Level-1 (rows 0..15 scanned): lambda_2 >= 8*sigmoid(m); zero certified iff
//   m >= logit(0.0125) = -4.36945...  (use -4.3694, conservative)
#define L1_THRESH -4.3694f
// Level-2 (full scan): lambda_2 >= 64*sigmoid(m2); zero certified iff
//   m2 >= logit(0.0015625) = -6.459905... (use -6.4599, conservative)
#define L2_THRESH -6.4599f
#define PEN_SCALE 1099511627776.0   // 2^40 fixed-point, order-independent accumulation

__device__ unsigned long long g_acc;            // fixed-point penalty accumulator
__device__ unsigned int       g_count;          // warp completion counter
__device__ unsigned int       g_nfail;          // # batches needing eigensolve
__device__ int                g_fail[BATCH];    // their indices

__device__ __forceinline__ float warp_sum(float v) {
    #pragma unroll
    for (int o = 16; o > 0; o >>= 1)
        v += __shfl_xor_sync(0xffffffffu, v, o);
    return v;
}

// ======== 32-thread (single-warp) exact eigensolve for one batch ========
// Each lane owns rows {lane, lane+32}. Only __syncwarp, no block sync.
__device__ void warp_eig(const float* __restrict__ src, int lane,
                         float M[NN][NN + 1], float* u, float* w,
                         float* dd, float* ee2) {
    // load + sigmoid
    for (int idx = lane; idx < NN * NN; idx += 32) {
        float x = src[idx];
        M[idx >> 6][idx & 63] = 1.0f / (1.0f + expf(-x));
    }
    __syncwarp();

    // degree & diagonal stash
    float diag[2];
    #pragma unroll
    for (int h = 0; h < 2; h++) {
        int r = lane + 32 * h;
        float deg = 0.0f;
        #pragma unroll 8
        for (int j = 0; j < NN; j++) deg += M[r][j];
        diag[h] = deg - M[r][r];
    }
    __syncwarp();

    // symmetrize off-diagonals: pair (i,j), i<j handled by owner of row i
    #pragma unroll
    for (int h = 0; h < 2; h++) {
        int r = lane + 32 * h;
        for (int j = r + 1; j < NN; j++) {
            float v = -0.5f * (M[r][j] + M[j][r]);
            M[r][j] = v;
            M[j][r] = v;
        }
    }
    __syncwarp();
    #pragma unroll
    for (int h = 0; h < 2; h++) M[lane + 32 * h][lane + 32 * h] = diag[h];
    __syncwarp();

    // Householder tridiagonalization, 2 rows per lane
    for (int k = 0; k < NN - 2; k++) {
        float xi2 = 0.0f;
        #pragma unroll
        for (int h = 0; h < 2; h++) {
            int r = lane + 32 * h;
            if (r > k) { float x = M[r][k]; xi2 += x * x; }
        }
        float sigma = warp_sum(xi2);

        float x1 = M[k + 1][k];
        float nrm = sqrtf(sigma);
        float alpha = (x1 >= 0.0f) ? -nrm : nrm;
        if (lane == 0) ee2[k] = sigma;

        float vnorm2 = 2.0f * (sigma - x1 * alpha);
        float invv = 2.0f / fmaxf(vnorm2, 1e-30f);

        #pragma unroll
        for (int h = 0; h < 2; h++) {
            int r = lane + 32 * h;
            float vi = (r > k) ? M[r][k] : 0.0f;
            if (r == k + 1) vi -= alpha;
            u[r] = vi;
        }
        __syncwarp();

        float pv[2];
        float sloc = 0.0f;
        #pragma unroll
        for (int h = 0; h < 2; h++) {
            int r = lane + 32 * h;
            float pi = 0.0f;
            if (r > k) {
                #pragma unroll 4
                for (int j = k + 1; j < NN; j++) pi += M[r][j] * u[j];
                pi *= invv;
            }
            pv[h] = pi;
            sloc += u[r] * pi;
        }
        float s = warp_sum(sloc);
        float K = 0.5f * invv * s;
        #pragma unroll
        for (int h = 0; h < 2; h++) {
            int r = lane + 32 * h;
            w[r] = pv[h] - K * u[r];
        }
        __syncwarp();

        #pragma unroll
        for (int h = 0; h < 2; h++) {
            int r = lane + 32 * h;
            if (r > k) {
                float vloc = u[r];
                float wloc = w[r];
                #pragma unroll 4
                for (int j = k + 1; j < NN; j++)
                    M[r][j] -= vloc * w[j] + wloc * u[j];
            }
        }
        __syncwarp();
    }

    #pragma unroll
    for (int h = 0; h < 2; h++) {
        int r = lane + 32 * h;
        dd[r] = M[r][r];
    }
    if (lane == 0) {
        float t = M[NN - 1][NN - 2];
        ee2[NN - 2] = t * t;
        ee2[NN - 1] = 0.0f;
    }
    __syncwarp();

    // multisection bisection for lambda_2 (Sturm negcount), 32 lanes
    float gl = 1e30f, gu = -1e30f;
    for (int i = lane; i < NN; i += 32) {
        float ei  = sqrtf(ee2[i]);
        float eim = (i > 0) ? sqrtf(ee2[i - 1]) : 0.0f;
        float r = ei + eim;
        gl = fminf(gl, dd[i] - r);
        gu = fmaxf(gu, dd[i] + r);
    }
    #pragma unroll
    for (int o = 16; o > 0; o >>= 1) {
        gl = fminf(gl, __shfl_xor_sync(0xffffffffu, gl, o));
        gu = fmaxf(gu, __shfl_xor_sync(0xffffffffu, gu, o));
    }

    float lo = gl, hi = gu;
    #pragma unroll 1
    for (int round = 0; round < 6; round++) {
        float stepw = (hi - lo) * (1.0f / 33.0f);
        float x = lo + stepw * (float)(lane + 1);
        float q = dd[0] - x;
        int c = (q < 0.0f);
        #pragma unroll 1
        for (int i = 1; i < NN; i++) {
            float den = q;
            if (fabsf(den) < 1e-30f) den = -1e-30f;
            q = dd[i] - x - ee2[i - 1] / den;
            c += (q < 0.0f);
        }
        unsigned bal = __ballot_sync(0xffffffffu, c >= 2);
        if (bal == 0u) {
            lo += stepw * 32.0f;
        } else {
            int t = __ffs(bal) - 1;
            hi = lo + stepw * (float)(t + 1);
            lo += stepw * (float)t;
        }
    }
    float lambda2 = 0.5f * (lo + hi);
    if (lane == 0) {
        float pen = fmaxf(0.0f, EPS_PEN - lambda2);
        unsigned long long q = (unsigned long long)((double)pen * PEN_SCALE);
        atomicAdd(&g_acc, q);   // order-independent => deterministic
    }
    __syncwarp();
}

__global__ void __launch_bounds__(TPB)
spectral_kernel(const float* __restrict__ logits, float* __restrict__ out) {
    __shared__ float M[NN][NN + 1];
    __shared__ float u[NN];
    __shared__ float w[NN];
    __shared__ float dd[NN];
    __shared__ float ee2[NN];

    const int tid  = threadIdx.x;
    const int lane = tid & 31;
    const int b    = blockIdx.x * (TPB / 32) + (tid >> 5);   // one batch per warp

    // publish the all-certified answer immediately; the last warp overwrites it
    // only if some batch actually needs the eigensolve (ordered via fence+counter).
    if (blockIdx.x == 0 && tid == 0) out[0] = 0.0f;

    // ======== LEVEL 1: scan rows 0..15 (256 float4), warp-local ========
    // Scanned subgraph contains join(K16, empty48) => lambda_2(M) >= 8*sigmoid(m).
    const float4* src4 = (const float4*)(logits + (size_t)b * NN * NN);
    float m = 1e30f;
    #pragma unroll
    for (int i = 0; i < 8; i++) {
        float4 v = __ldg(src4 + lane + 32 * i);
        m = fminf(m, fminf(fminf(v.x, v.y), fminf(v.z, v.w)));
    }
    unsigned esc = __ballot_sync(0xffffffffu, m < L1_THRESH);

    if (esc != 0u) {
        // ======== LEVEL 2 (rare): full scan, bound 64*sigmoid(m2) ========
        #pragma unroll 4
        for (int i = 8; i < 32; i++) {
            float4 v = __ldg(src4 + lane + 32 * i);
            m = fminf(m, fminf(fminf(v.x, v.y), fminf(v.z, v.w)));
        }
        #pragma unroll
        for (int o = 16; o > 0; o >>= 1)
            m = fminf(m, __shfl_xor_sync(0xffffffffu, m, o));
        if (m < L2_THRESH && lane == 0) {
            // certificate failed outright: queue for exact eigensolve
            unsigned int slot = atomicAdd(&g_nfail, 1u);
            g_fail[slot] = b;
        }
    }

    // ======== last-WARP-done: no block barrier anywhere ========
    unsigned int old = 0u;
    if (lane == 0) {
        __threadfence();                      // release: fail-list / out[0]=0
        old = atomicAdd(&g_count, 1u);
    }
    old = __shfl_sync(0xffffffffu, old, 0);

    if (old == NWARPS - 1u) {                 // globally last warp
        __threadfence();                      // acquire
        unsigned int nf = *((volatile unsigned int*)&g_nfail);
        if (nf != 0u) {
            for (unsigned int i = 0; i < nf; i++) {
                int fb = ((volatile int*)g_fail)[i];
                warp_eig(logits + (size_t)fb * NN * NN, lane, M, u, w, dd, ee2);
            }
            if (lane == 0) {
                unsigned long long a = g_acc;
                out[0] = (float)((double)a * (1.0 / PEN_SCALE) * (1.0 / (double)BATCH));
                g_acc = 0ull;
                g_nfail = 0u;
            }
        }
        if (lane == 0) {
            __threadfence();
            g_count = 0u;   // reset for next graph replay
        }
    }
}

extern "C" void kernel_launch(void* const* d_in, const int* in_sizes, int n_in,
                              void* d_out, int out_size) {
    const float* logits = (const float*)d_in[0];   // [4096, 64, 64] float32
    // d_in[1] = node_types (int64) — unused by the reference computation
    float* out = (float*)d_out;

    spectral_kernel<<<NBLK, TPB>>>(logits, out);
}

// round 17
// speedup vs baseline: 1.1093x; 1.1093x over previous
#include <cuda_runtime.h>
#include <cuda_bf16.h>
#include <math.h>

#define NN 64
#define BATCH 4096
#define TPB 512
#define NBLK (BATCH / (TPB / 32))   // 256 blocks: 16 warps/CTA, one batch per warp
#define EPS_PEN 0.1f
// Level-1 (rows 0..15 scanned): lambda_2 >= 8*sigmoid(m); zero certified iff
//   m >= logit(0.0125) = -4.36945...  (use -4.3694, conservative)
#define L1_THRESH -4.3694f
// Level-2 (full scan): lambda_2 >= 64*sigmoid(m2); zero certified iff
//   m2 >= logit(0.0015625) = -6.459905... (use -6.4599, conservative)
#define L2_THRESH -6.4599f
#define PEN_SCALE 1099511627776.0   // 2^40 fixed-point, order-independent accumulation

__device__ unsigned long long g_acc;            // fixed-point penalty accumulator
__device__ unsigned int       g_count;          // block completion counter
__device__ unsigned int       g_nfail;          // # batches needing eigensolve
__device__ int                g_fail[BATCH];    // their indices

__device__ __forceinline__ float warp_sum(float v) {
    #pragma unroll
    for (int o = 16; o > 0; o >>= 1)
        v += __shfl_xor_sync(0xffffffffu, v, o);
    return v;
}

// ======== 32-thread (single-warp) exact eigensolve for one batch ========
// Each lane owns rows {lane, lane+32}. Only __syncwarp, no block sync.
__device__ void warp_eig(const float* __restrict__ src, int lane,
                         float M[NN][NN + 1], float* u, float* w,
                         float* dd, float* ee2) {
    // load + sigmoid
    for (int idx = lane; idx < NN * NN; idx += 32) {
        float x = src[idx];
        M[idx >> 6][idx & 63] = 1.0f / (1.0f + expf(-x));
    }
    __syncwarp();

    // degree & future diagonal
    float diag[2];
    #pragma unroll
    for (int h = 0; h < 2; h++) {
        int r = lane + 32 * h;
        float deg = 0.0f;
        #pragma unroll 8
        for (int j = 0; j < NN; j++) deg += M[r][j];
        diag[h] = deg - M[r][r];
    }
    __syncwarp();

    // symmetrize: pair (i,j), i<j handled by owner of row i
    #pragma unroll
    for (int h = 0; h < 2; h++) {
        int r = lane + 32 * h;
        for (int j = r + 1; j < NN; j++) {
            float v = -0.5f * (M[r][j] + M[j][r]);
            M[r][j] = v;
            M[j][r] = v;
        }
    }
    __syncwarp();
    #pragma unroll
    for (int h = 0; h < 2; h++) M[lane + 32 * h][lane + 32 * h] = diag[h];
    __syncwarp();

    // Householder tridiagonalization, 2 rows per lane
    for (int k = 0; k < NN - 2; k++) {
        float xi2 = 0.0f;
        #pragma unroll
        for (int h = 0; h < 2; h++) {
            int r = lane + 32 * h;
            if (r > k) { float x = M[r][k]; xi2 += x * x; }
        }
        float sigma = warp_sum(xi2);

        float x1 = M[k + 1][k];
        float nrm = sqrtf(sigma);
        float alpha = (x1 >= 0.0f) ? -nrm : nrm;
        if (lane == 0) ee2[k] = sigma;

        float vnorm2 = 2.0f * (sigma - x1 * alpha);
        float invv = 2.0f / fmaxf(vnorm2, 1e-30f);

        #pragma unroll
        for (int h = 0; h < 2; h++) {
            int r = lane + 32 * h;
            float vi = (r > k) ? M[r][k] : 0.0f;
            if (r == k + 1) vi -= alpha;
            u[r] = vi;
        }
        __syncwarp();

        float pv[2];
        float sloc = 0.0f;
        #pragma unroll
        for (int h = 0; h < 2; h++) {
            int r = lane + 32 * h;
            float pi = 0.0f;
            if (r > k) {
                #pragma unroll 4
                for (int j = k + 1; j < NN; j++) pi += M[r][j] * u[j];
                pi *= invv;
            }
            pv[h] = pi;
            sloc += u[r] * pi;
        }
        float s = warp_sum(sloc);
        float K = 0.5f * invv * s;
        #pragma unroll
        for (int h = 0; h < 2; h++) {
            int r = lane + 32 * h;
            w[r] = pv[h] - K * u[r];
        }
        __syncwarp();

        #pragma unroll
        for (int h = 0; h < 2; h++) {
            int r = lane + 32 * h;
            if (r > k) {
                float vloc = u[r];
                float wloc = w[r];
                #pragma unroll 4
                for (int j = k + 1; j < NN; j++)
                    M[r][j] -= vloc * w[j] + wloc * u[j];
            }
        }
        __syncwarp();
    }

    #pragma unroll
    for (int h = 0; h < 2; h++) {
        int r = lane + 32 * h;
        dd[r] = M[r][r];
    }
    if (lane == 0) {
        float t = M[NN - 1][NN - 2];
        ee2[NN - 2] = t * t;
        ee2[NN - 1] = 0.0f;
    }
    __syncwarp();

    // multisection bisection for lambda_2 (Sturm negcount), 32 lanes
    float gl = 1e30f, gu = -1e30f;
    for (int i = lane; i < NN; i += 32) {
        float ei  = sqrtf(ee2[i]);
        float eim = (i > 0) ? sqrtf(ee2[i - 1]) : 0.0f;
        float r = ei + eim;
        gl = fminf(gl, dd[i] - r);
        gu = fmaxf(gu, dd[i] + r);
    }
    #pragma unroll
    for (int o = 16; o > 0; o >>= 1) {
        gl = fminf(gl, __shfl_xor_sync(0xffffffffu, gl, o));
        gu = fmaxf(gu, __shfl_xor_sync(0xffffffffu, gu, o));
    }

    float lo = gl, hi = gu;
    #pragma unroll 1
    for (int round = 0; round < 6; round++) {
        float stepw = (hi - lo) * (1.0f / 33.0f);
        float x = lo + stepw * (float)(lane + 1);
        float q = dd[0] - x;
        int c = (q < 0.0f);
        #pragma unroll 1
        for (int i = 1; i < NN; i++) {
            float den = q;
            if (fabsf(den) < 1e-30f) den = -1e-30f;
            q = dd[i] - x - ee2[i - 1] / den;
            c += (q < 0.0f);
        }
        unsigned bal = __ballot_sync(0xffffffffu, c >= 2);
        if (bal == 0u) {
            lo += stepw * 32.0f;
        } else {
            int t = __ffs(bal) - 1;
            hi = lo + stepw * (float)(t + 1);
            lo += stepw * (float)t;
        }
    }
    float lambda2 = 0.5f * (lo + hi);
    if (lane == 0) {
        float pen = fmaxf(0.0f, EPS_PEN - lambda2);
        unsigned long long q = (unsigned long long)((double)pen * PEN_SCALE);
        atomicAdd(&g_acc, q);   // order-independent => deterministic
    }
    __syncwarp();
}

__global__ void __launch_bounds__(TPB)
spectral_kernel(const float* __restrict__ logits, float* __restrict__ out) {
    __shared__ float M[NN][NN + 1];
    __shared__ float u[NN];
    __shared__ float w[NN];
    __shared__ float dd[NN];
    __shared__ float ee2[NN];

    const int tid  = threadIdx.x;
    const int lane = tid & 31;
    const int b    = blockIdx.x * (TPB / 32) + (tid >> 5);   // one batch per warp

    // publish the all-certified answer immediately; the drain below overwrites it
    // only if some batch actually needs the eigensolve (ordered by fence+counter).
    if (blockIdx.x == 0 && tid == 0) out[0] = 0.0f;

    // ======== LEVEL 1: scan rows 0..15 (256 float4), warp-local, no barriers ====
    // Scanned subgraph contains join(K16, empty48) => lambda_2(M) >= 8*sigmoid(m).
    const float4* src4 = (const float4*)(logits + (size_t)b * NN * NN);
    float m = 1e30f;
    #pragma unroll
    for (int i = 0; i < 8; i++) {
        float4 v = __ldg(src4 + lane + 32 * i);
        m = fminf(m, fminf(fminf(v.x, v.y), fminf(v.z, v.w)));
    }
    unsigned esc = __ballot_sync(0xffffffffu, m < L1_THRESH);

    if (esc != 0u) {
        // ======== LEVEL 2 (rare): full scan of this batch, bound 64*sigmoid(m2) ====
        #pragma unroll 4
        for (int i = 8; i < 32; i++) {
            float4 v = __ldg(src4 + lane + 32 * i);
            m = fminf(m, fminf(fminf(v.x, v.y), fminf(v.z, v.w)));
        }
        #pragma unroll
        for (int o = 16; o > 0; o >>= 1)
            m = fminf(m, __shfl_xor_sync(0xffffffffu, m, o));
        if (m < L2_THRESH && lane == 0) {
            // certificate failed outright: queue for exact eigensolve
            unsigned int slot = atomicAdd(&g_nfail, 1u);
            g_fail[slot] = b;
        }
    }

    // ======== one barrier, then warp 0 owns the tail; warps 1..15 retire ========
    __syncthreads();
    if (tid < 32) {
        unsigned int old = 0u;
        if (lane == 0) {
            __threadfence();                   // release: fail-list / out[0]=0
            old = atomicAdd(&g_count, 1u);     // one atomic per block (256 total)
        }
        old = __shfl_sync(0xffffffffu, old, 0);

        if (old == NBLK - 1u) {                // globally last block
            __threadfence();                   // acquire
            unsigned int nf = *((volatile unsigned int*)&g_nfail);
            if (nf != 0u) {
                for (unsigned int i = 0; i < nf; i++) {
                    int fb = ((volatile int*)g_fail)[i];
                    warp_eig(logits + (size_t)fb * NN * NN, lane, M, u, w, dd, ee2);
                }
                if (lane == 0) {
                    unsigned long long a = g_acc;
                    out[0] = (float)((double)a * (1.0 / PEN_SCALE) * (1.0 / (double)BATCH));
                    g_acc = 0ull;
                    g_nfail = 0u;
                }
            }
            if (lane == 0) {
                __threadfence();
                g_count = 0u;   // reset for next graph replay
            }
        }
    }
}

extern "C" void kernel_launch(void* const* d_in, const int* in_sizes, int n_in,
                              void* d_out, int out_size) {
    const float* logits = (const float*)d_in[0];   // [4096, 64, 64] float32
    // d_in[1] = node_types (int64) — unused by the reference computation
    float* out = (float*)d_out;

    spectral_kernel<<<NBLK, TPB>>>(logits, out);
}